// round 10
// baseline (speedup 1.0000x reference)
#include <cuda_runtime.h>
#include <cuda_fp16.h>
#include <cuda_fp8.h>
#include <cstdint>
#include <cstddef>

#define N_NODES 8192
#define D_FEAT  1024
#define ROW_BYTES 32768   // per row: 256 blocks x 128B ( [h 64B | e4m3 32B | e5m2 32B] )

#if defined(__CUDA_ARCH_FEAT_SM103_ALL) || defined(__CUDA_ARCH_FEAT_SM100_ALL) || \
    defined(__CUDA_ARCH_FEAT_SM101_ALL) || defined(__CUDA_ARCH_SPECIFIC__) ||     \
    defined(__CUDA_ARCH_FAMILY_SPECIFIC__)
#define HAS_TCG 1
#else
#define HAS_TCG 0
#endif

__device__ const int g_has_tcg = HAS_TCG;

// Scratch (static device globals -- no allocation allowed)
__device__ float   g_dinv[N_NODES];
__device__ uint8_t g_A2[(size_t)N_NODES * ROW_BYTES];  // 268 MB: A split rows (strided)
__device__ uint8_t g_B2[(size_t)D_FEAT * ROW_BYTES];   // 33.5 MB: (64*G)^T split rows

__device__ __forceinline__ uint16_t cvt2_e4m3(float a, float b) {
    return (uint16_t)__nv_cvt_float2_to_fp8x2(make_float2(a, b), __NV_SATFINITE, __NV_E4M3);
}
__device__ __forceinline__ uint16_t cvt2_e5m2(float a, float b) {
    return (uint16_t)__nv_cvt_float2_to_fp8x2(make_float2(a, b), __NV_SATFINITE, __NV_E5M2);
}
__device__ __forceinline__ uint8_t f2e4m3(float f) {
    return (uint8_t)__nv_cvt_float_to_fp8(f, __NV_SATFINITE, __NV_E4M3);
}
__device__ __forceinline__ uint8_t f2e5m2(float f) {
    return (uint8_t)__nv_cvt_float_to_fp8(f, __NV_SATFINITE, __NV_E5M2);
}

// ---------------------------------------------------------------------------
// Kernel 1: fused row sums + A split (fp16 high / e4m3 full / e5m2 residual)
// Packed HW conversions (f16x2 / e4m3x2 / e5m2x2).
// ---------------------------------------------------------------------------
__global__ void rowsum_convert_kernel(const float* __restrict__ Mat) {
    __shared__ float red[256];
    int row = blockIdx.x;
    const float4* p = reinterpret_cast<const float4*>(Mat + (size_t)row * N_NODES);
    uint8_t* dst = g_A2 + (size_t)row * ROW_BYTES;
    float s = 0.f;
    for (int i = threadIdx.x; i < N_NODES / 8; i += 256) {
        float4 v0 = p[i * 2];
        float4 v1 = p[i * 2 + 1];
        s += (v0.x + v0.y) + (v0.z + v0.w) + (v1.x + v1.y) + (v1.z + v1.w);
        float f[8] = {v0.x, v0.y, v0.z, v0.w, v1.x, v1.y, v1.z, v1.w};
        uint32_t Hp[4];
        uint16_t pa[4], pl[4];
#pragma unroll
        for (int q = 0; q < 4; q++) {
            __half2 h2 = __floats2half2_rn(f[2 * q], f[2 * q + 1]);
            Hp[q] = *reinterpret_cast<uint32_t*>(&h2);
            float2 hf = __half22float2(h2);
            pa[q] = cvt2_e4m3(f[2 * q], f[2 * q + 1]);
            pl[q] = cvt2_e5m2(f[2 * q] - hf.x, f[2 * q + 1] - hf.y);
        }
        uint4 H;
        H.x = Hp[0]; H.y = Hp[1]; H.z = Hp[2]; H.w = Hp[3];
        uint64_t PA = (uint64_t)pa[0] | ((uint64_t)pa[1] << 16) |
                      ((uint64_t)pa[2] << 32) | ((uint64_t)pa[3] << 48);
        uint64_t PL = (uint64_t)pl[0] | ((uint64_t)pl[1] << 16) |
                      ((uint64_t)pl[2] << 32) | ((uint64_t)pl[3] << 48);
        int k = i * 8;
        int blk = k >> 5, pos = k & 31;
        uint8_t* b = dst + (size_t)blk * 128;
        *reinterpret_cast<uint4*>(b + pos * 2) = H;
        *reinterpret_cast<uint64_t*>(b + 64 + pos) = PA;
        *reinterpret_cast<uint64_t*>(b + 96 + pos) = PL;
    }
    red[threadIdx.x] = s;
    __syncthreads();
    for (int off = 128; off > 0; off >>= 1) {
        if (threadIdx.x < off) red[threadIdx.x] += red[threadIdx.x + off];
        __syncthreads();
    }
    if (threadIdx.x == 0) g_dinv[row] = rsqrtf(red[0] + 1e-8f);
}

// ---------------------------------------------------------------------------
// Kernel 2: B2[j] = split of (64 * F[k][j] * dinv[k])^T
// ---------------------------------------------------------------------------
__global__ void scale_transpose_kernel(const float* __restrict__ F) {
    __shared__ float tile[32][33];
    int jb = blockIdx.x * 32;
    int kb = blockIdx.y * 32;
    int tx = threadIdx.x;
    for (int r = threadIdx.y; r < 32; r += 8) {
        int k = kb + r;
        tile[r][tx] = F[(size_t)k * D_FEAT + jb + tx] * g_dinv[k];
    }
    __syncthreads();
    for (int r = threadIdx.y; r < 32; r += 8) {
        float a = tile[tx][r] * 64.0f;
        __half h = __float2half_rn(a);
        uint8_t* b = g_B2 + (size_t)(jb + r) * ROW_BYTES + (size_t)(kb >> 5) * 128;
        *reinterpret_cast<__half*>(b + tx * 2) = h;
        b[64 + tx] = f2e4m3(a);
        b[96 + tx] = f2e5m2(a - __half2float(h));
    }
}

// ---------------------------------------------------------------------------
// Kernel 3: cg2 (2-CTA) mixed fp16/fp8 3-pass tcgen05 GEMM.
//   Pair tile: M=512, N=256. Each CTA: A 32KB (256 rows), B 16KB (N/2 rows).
//   acc = Ah@Gh (f16) + A8@Gl8 + Al8@G8 ;  out = dinv_row * 2^-6 * acc
// ---------------------------------------------------------------------------
#define PAIR_M 512
#define TILE_N 256
#define STAGES 4
#define K_ITERS 256

#define A_STAGE_BYTES 32768              // 2 x 128 rows x 128B
#define B_STAGE_BYTES 16384              // 128 rows x 128B
#define STAGE_BYTES   (A_STAGE_BYTES + B_STAGE_BYTES)   // 48 KB
#define SMEM_AOF(s)   ((s) * STAGE_BYTES)
#define SMEM_BOF(s)   ((s) * STAGE_BYTES + A_STAGE_BYTES)
#define SMEM_CTRL     (STAGES * STAGE_BYTES)            // 196608
#define SMEM_TMEM_PTR (SMEM_CTRL)
#define SMEM_FULL(s)  (SMEM_CTRL + 16 + (s) * 8)
#define SMEM_DONE(s)  (SMEM_CTRL + 48 + (s) * 8)
#define SMEM_TOTAL    (SMEM_CTRL + 96 + 1024)

// idesc: cformat F32=1@[4:6), a/bformat@[7:10)/[10:13), N/8@[17:23), M/16@[24:29)
#define IDESC_F16 ((1u << 4) | ((TILE_N / 8) << 17) | ((256 / 16) << 24))
#define IDESC_F8(AT, BT) ((1u << 4) | ((AT) << 7) | ((BT) << 10) | ((TILE_N / 8) << 17) | ((256 / 16) << 24))

__device__ __forceinline__ uint32_t smem_u32(const void* p) {
    uint32_t a;
    asm("{ .reg .u64 t; cvta.to.shared.u64 t, %1; cvt.u32.u64 %0, t; }" : "=r"(a) : "l"(p));
    return a;
}
__device__ __forceinline__ uint32_t elect_one() {
    uint32_t pred;
    asm volatile("{\n\t.reg .pred p;\n\telect.sync _|p, 0xFFFFFFFF;\n\t"
                 "selp.b32 %0, 1, 0, p;\n\t}" : "=r"(pred));
    return pred;
}
__device__ __forceinline__ uint64_t make_desc(uint32_t addr) {
    constexpr uint64_t BASE = (uint64_t(2) << 61) | (uint64_t(1) << 46) |
                              (uint64_t(64) << 32) | (uint64_t(1) << 16);
    return BASE | ((uint64_t)(addr >> 4) & 0x3FFF);
}
__device__ __forceinline__ void cpasync16(uint32_t dst, const void* src) {
    asm volatile("cp.async.cg.shared.global [%0], [%1], 16;" :: "r"(dst), "l"(src));
}
__device__ __forceinline__ void mbar_wait(uint32_t mbar, uint32_t parity) {
    uint32_t done;
    asm volatile("{\n\t.reg .pred p;\n\t"
                 "mbarrier.try_wait.parity.acquire.cta.shared::cta.b64 p, [%1], %2;\n\t"
                 "selp.b32 %0, 1, 0, p;\n\t}"
                 : "=r"(done) : "r"(mbar), "r"(parity) : "memory");
    while (!done) {
        asm volatile("{\n\t.reg .pred p;\n\t"
                     "mbarrier.try_wait.parity.acquire.cta.shared::cta.b64 p, [%1], %2, 0x989680;\n\t"
                     "selp.b32 %0, 1, 0, p;\n\t}"
                     : "=r"(done) : "r"(mbar), "r"(parity) : "memory");
    }
}

#if HAS_TCG
__device__ __forceinline__ void mma_f16_cg2(uint32_t d, uint64_t a, uint64_t b,
                                            uint32_t idesc, uint32_t enable) {
    asm volatile("{\n\t.reg .pred p;\n\tsetp.ne.u32 p, %4, 0;\n\t"
                 "tcgen05.mma.cta_group::2.kind::f16 [%0], %1, %2, %3, "
                 "{%5, %5, %5, %5, %5, %5, %5, %5}, p;\n\t}"
                 :: "r"(d), "l"(a), "l"(b), "r"(idesc), "r"(enable), "r"(0u) : "memory");
}
__device__ __forceinline__ void mma_f8_cg2(uint32_t d, uint64_t a, uint64_t b,
                                           uint32_t idesc, uint32_t enable) {
    asm volatile("{\n\t.reg .pred p;\n\tsetp.ne.u32 p, %4, 0;\n\t"
                 "tcgen05.mma.cta_group::2.kind::f8f6f4 [%0], %1, %2, %3, "
                 "{%5, %5, %5, %5, %5, %5, %5, %5}, p;\n\t}"
                 :: "r"(d), "l"(a), "l"(b), "r"(idesc), "r"(enable), "r"(0u) : "memory");
}
__device__ __forceinline__ void ldtm_x32(uint32_t* r, uint32_t taddr) {
    asm volatile(
        "tcgen05.ld.sync.aligned.32x32b.x32.b32 "
        "{%0, %1, %2, %3, %4, %5, %6, %7, "
        " %8, %9, %10, %11, %12, %13, %14, %15, "
        " %16, %17, %18, %19, %20, %21, %22, %23, "
        " %24, %25, %26, %27, %28, %29, %30, %31}, [%32];"
        : "=r"(r[0]),  "=r"(r[1]),  "=r"(r[2]),  "=r"(r[3]),
          "=r"(r[4]),  "=r"(r[5]),  "=r"(r[6]),  "=r"(r[7]),
          "=r"(r[8]),  "=r"(r[9]),  "=r"(r[10]), "=r"(r[11]),
          "=r"(r[12]), "=r"(r[13]), "=r"(r[14]), "=r"(r[15]),
          "=r"(r[16]), "=r"(r[17]), "=r"(r[18]), "=r"(r[19]),
          "=r"(r[20]), "=r"(r[21]), "=r"(r[22]), "=r"(r[23]),
          "=r"(r[24]), "=r"(r[25]), "=r"(r[26]), "=r"(r[27]),
          "=r"(r[28]), "=r"(r[29]), "=r"(r[30]), "=r"(r[31])
        : "r"(taddr));
}
#endif  // HAS_TCG

// Per-CTA stage load: A = 2 blocks of 128 rows (mma-half0/1), B = 128 rows.
__device__ __forceinline__ void load_stage(uint32_t smem_base, int s, int kiter,
                                           int a_row0, int a_row1, int b_row0, int tid) {
    uint32_t a0 = smem_base + SMEM_AOF(s);
    uint32_t b0 = smem_base + SMEM_BOF(s);
    const uint8_t* gA0 = g_A2 + (size_t)a_row0 * ROW_BYTES + (size_t)kiter * 128;
    const uint8_t* gA1 = g_A2 + (size_t)a_row1 * ROW_BYTES + (size_t)kiter * 128;
    const uint8_t* gB  = g_B2 + (size_t)b_row0 * ROW_BYTES + (size_t)kiter * 128;
#pragma unroll
    for (int i = 0; i < 8; i++) {           // A half0: 128 rows x 128B
        int idx = tid + i * 128;
        int row = idx >> 3, c = idx & 7;
        uint32_t off = (uint32_t)row * 128 + c * 16;
        uint32_t sw = off ^ ((off >> 3) & 0x70);
        cpasync16(a0 + sw, gA0 + (size_t)row * ROW_BYTES + c * 16);
    }
#pragma unroll
    for (int i = 0; i < 8; i++) {           // A half1
        int idx = tid + i * 128;
        int row = idx >> 3, c = idx & 7;
        uint32_t off = (uint32_t)row * 128 + c * 16;
        uint32_t sw = off ^ ((off >> 3) & 0x70);
        cpasync16(a0 + 16384 + sw, gA1 + (size_t)row * ROW_BYTES + c * 16);
    }
#pragma unroll
    for (int i = 0; i < 8; i++) {           // B: 128 rows x 128B
        int idx = tid + i * 128;
        int row = idx >> 3, c = idx & 7;
        uint32_t off = (uint32_t)row * 128 + c * 16;
        uint32_t sw = off ^ ((off >> 3) & 0x70);
        cpasync16(b0 + sw, gB + (size_t)row * ROW_BYTES + c * 16);
    }
}

__global__ void __launch_bounds__(128, 1) __cluster_dims__(2, 1, 1)
gcn_gemm_kernel(float* __restrict__ out) {
#if HAS_TCG
    if (!g_has_tcg) return;
    extern __shared__ char smem[];
    uint32_t smem_base = (smem_u32(smem) + 1023u) & ~1023u;
    int tid = threadIdx.x;
    int wid = tid >> 5;
    int lid = tid & 31;
    uint32_t rank;
    asm("mov.u32 %0, %%cluster_ctarank;" : "=r"(rank));
    int pair = blockIdx.x >> 1;
    int mbase = pair * PAIR_M;
    int n0 = blockIdx.y * TILE_N;
    int a_row0 = mbase + (int)rank * 128;
    int a_row1 = mbase + 256 + (int)rank * 128;
    int b_row0 = n0 + (int)rank * 128;      // cg2 B split: N/2 rows per CTA

    if (tid == 0) {
#pragma unroll
        for (int s = 0; s < STAGES; s++) {
            asm volatile("mbarrier.init.shared.b64 [%0], %1;"
                         :: "r"(smem_base + SMEM_FULL(s)), "r"(2u) : "memory");
            asm volatile("mbarrier.init.shared.b64 [%0], %1;"
                         :: "r"(smem_base + SMEM_DONE(s)), "r"(1u) : "memory");
        }
    }
    if (wid == 0) {
        asm volatile("tcgen05.alloc.cta_group::2.sync.aligned.shared::cta.b32 [%0], %1;"
                     :: "r"(smem_base + SMEM_TMEM_PTR), "r"(512u) : "memory");
    }
    __syncthreads();
    asm volatile("barrier.cluster.arrive.aligned;" ::: "memory");
    asm volatile("barrier.cluster.wait.aligned;" ::: "memory");

    uint32_t tb;
    asm volatile("ld.shared.b32 %0, [%1];" : "=r"(tb) : "r"(smem_base + SMEM_TMEM_PTR));

    // Prologue: fill stages 0 .. STAGES-2
#pragma unroll
    for (int p = 0; p < STAGES - 1; p++) {
        load_stage(smem_base, p, p, a_row0, a_row1, b_row0, tid);
        asm volatile("cp.async.commit_group;" ::: "memory");
    }

    for (int k = 0; k < K_ITERS; k++) {
        int s = k % STAGES;
        int pend = K_ITERS - 1 - k;
        if (pend >= STAGES - 2) {
            asm volatile("cp.async.wait_group %0;" :: "n"(STAGES - 2) : "memory");
        } else if (pend == 1) {
            asm volatile("cp.async.wait_group 1;" ::: "memory");
        } else {
            asm volatile("cp.async.wait_group 0;" ::: "memory");
        }
        __syncthreads();

        // Signal leader: this CTA's stage s is loaded.
        if (tid == 0) {
            asm volatile("fence.proxy.async.shared::cta;" ::: "memory");
            if (rank == 0) {
                asm volatile("mbarrier.arrive.shared.b64 _, [%0];"
                             :: "r"(smem_base + SMEM_FULL(s)) : "memory");
            } else {
                uint32_t rem;
                asm volatile("mapa.shared::cluster.u32 %0, %1, 0;"
                             : "=r"(rem) : "r"(smem_base + SMEM_FULL(s)));
                asm volatile("mbarrier.arrive.shared::cluster.b64 _, [%0];"
                             :: "r"(rem) : "memory");
            }
        }

        // Leader issues cg2 MMAs once both CTAs' stage s is ready.
        if (rank == 0 && wid == 0) {
            if (elect_one()) {
                mbar_wait(smem_base + SMEM_FULL(s), (uint32_t)((k / STAGES) & 1));
                uint32_t a_base = smem_base + SMEM_AOF(s);
                uint32_t b_base = smem_base + SMEM_BOF(s);
                uint64_t a0d = make_desc(a_base);           // pair M-half 0
                uint64_t a1d = make_desc(a_base + 16384);   // pair M-half 1
                uint64_t bd  = make_desc(b_base);
#pragma unroll
                for (int ks = 0; ks < 2; ks++) {            // fp16 Ah@Gh, K16 chunks
                    uint32_t en0 = (k > 0 || ks > 0) ? 1u : 0u;
                    mma_f16_cg2(tb,       a0d + 2 * ks, bd + 2 * ks, IDESC_F16, en0);
                    mma_f16_cg2(tb + 256, a1d + 2 * ks, bd + 2 * ks, IDESC_F16, en0);
                }
                mma_f8_cg2(tb,       a0d + 4, bd + 6, IDESC_F8(0, 1), 1u);   // A8@Gl8
                mma_f8_cg2(tb + 256, a1d + 4, bd + 6, IDESC_F8(0, 1), 1u);
                mma_f8_cg2(tb,       a0d + 6, bd + 4, IDESC_F8(1, 0), 1u);   // Al8@G8
                mma_f8_cg2(tb + 256, a1d + 6, bd + 4, IDESC_F8(1, 0), 1u);
                asm volatile(
                    "tcgen05.commit.cta_group::2.mbarrier::arrive::one.shared::cluster.multicast::cluster.b64 [%0], %1;"
                    :: "r"(smem_base + SMEM_DONE(s)), "h"((uint16_t)0x3) : "memory");
            }
        }

        int kn = k + STAGES - 1;
        if (kn < K_ITERS) {
            if (k > 0) {
                int t = (k - 1) % STAGES;   // stage to refill; its iter-(k-1) MMAs must be done
                mbar_wait(smem_base + SMEM_DONE(t), (uint32_t)(((k - 1) / STAGES) & 1));
            }
            load_stage(smem_base, kn % STAGES, kn, a_row0, a_row1, b_row0, tid);
            asm volatile("cp.async.commit_group;" ::: "memory");
        }
    }

    {
        int t = (K_ITERS - 1) % STAGES;
        mbar_wait(smem_base + SMEM_DONE(t), (uint32_t)(((K_ITERS - 1) / STAGES) & 1));
    }
    asm volatile("tcgen05.fence::after_thread_sync;" ::: "memory");

    // Epilogue: this CTA holds D rows rank*128.. of each pair M-half in its TMEM.
#pragma unroll
    for (int mh = 0; mh < 2; mh++) {
        int row = mbase + mh * 256 + (int)rank * 128 + wid * 32 + lid;
        float ds = g_dinv[row] * 0.015625f;
        float* orow = out + (size_t)row * D_FEAT + n0;
#pragma unroll
        for (int c = 0; c < 8; c++) {
            uint32_t r[32];
            ldtm_x32(r, tb + mh * 256 + c * 32);
            asm volatile("tcgen05.wait::ld.sync.aligned;" ::: "memory");
#pragma unroll
            for (int q = 0; q < 8; q++) {
                float4 v;
                v.x = __uint_as_float(r[q * 4 + 0]) * ds;
                v.y = __uint_as_float(r[q * 4 + 1]) * ds;
                v.z = __uint_as_float(r[q * 4 + 2]) * ds;
                v.w = __uint_as_float(r[q * 4 + 3]) * ds;
                *reinterpret_cast<float4*>(orow + c * 32 + q * 4) = v;
            }
        }
    }

    __syncthreads();
    if (wid == 0) {
        asm volatile("tcgen05.relinquish_alloc_permit.cta_group::2.sync.aligned;" ::: "memory");
        asm volatile("tcgen05.dealloc.cta_group::2.sync.aligned.b32 %0, %1;"
                     :: "r"(tb), "r"(512u));
    }
    asm volatile("barrier.cluster.arrive.aligned;" ::: "memory");
    asm volatile("barrier.cluster.wait.aligned;" ::: "memory");
#endif  // HAS_TCG
}

// ---------------------------------------------------------------------------
extern "C" void kernel_launch(void* const* d_in, const int* in_sizes, int n_in,
                              void* d_out, int out_size) {
    const float* features = (const float*)d_in[0];
    const float* Mat = (const float*)d_in[1];
    float* out = (float*)d_out;

    rowsum_convert_kernel<<<N_NODES, 256>>>(Mat);

    dim3 tpose_block(32, 8);
    dim3 tpose_grid(D_FEAT / 32, N_NODES / 32);
    scale_transpose_kernel<<<tpose_grid, tpose_block>>>(features);

    cudaFuncSetAttribute(gcn_gemm_kernel, cudaFuncAttributeMaxDynamicSharedMemorySize, SMEM_TOTAL);
    dim3 gemm_grid(N_NODES / PAIR_M * 2, D_FEAT / TILE_N);   // (32, 4), cluster (2,1)
    gcn_gemm_kernel<<<gemm_grid, 128, SMEM_TOTAL>>>(out);
}

// round 11
// speedup vs baseline: 1.0114x; 1.0114x over previous
#include <cuda_runtime.h>
#include <cuda_fp16.h>
#include <cuda_fp8.h>
#include <cstdint>
#include <cstddef>

#define N_NODES 8192
#define D_FEAT  1024
#define ROW_BYTES 32768   // per row: 256 blocks x 128B ( [h 64B | e4m3 32B | e5m2 32B] )

#if defined(__CUDA_ARCH_FEAT_SM103_ALL) || defined(__CUDA_ARCH_FEAT_SM100_ALL) || \
    defined(__CUDA_ARCH_FEAT_SM101_ALL) || defined(__CUDA_ARCH_SPECIFIC__) ||     \
    defined(__CUDA_ARCH_FAMILY_SPECIFIC__)
#define HAS_TCG 1
#else
#define HAS_TCG 0
#endif

__device__ const int g_has_tcg = HAS_TCG;

// Scratch (static device globals -- no allocation allowed)
__device__ float   g_dinv[N_NODES];
__device__ uint8_t g_A2[(size_t)N_NODES * ROW_BYTES];  // 268 MB: A split rows (strided)
__device__ uint8_t g_B2[(size_t)D_FEAT * ROW_BYTES];   // 33.5 MB: (64*G)^T split rows

__device__ __forceinline__ uint16_t cvt2_e4m3(float a, float b) {
    return (uint16_t)__nv_cvt_float2_to_fp8x2(make_float2(a, b), __NV_SATFINITE, __NV_E4M3);
}
__device__ __forceinline__ uint16_t cvt2_e5m2(float a, float b) {
    return (uint16_t)__nv_cvt_float2_to_fp8x2(make_float2(a, b), __NV_SATFINITE, __NV_E5M2);
}
__device__ __forceinline__ uint8_t f2e4m3(float f) {
    return (uint8_t)__nv_cvt_float_to_fp8(f, __NV_SATFINITE, __NV_E4M3);
}
__device__ __forceinline__ uint8_t f2e5m2(float f) {
    return (uint8_t)__nv_cvt_float_to_fp8(f, __NV_SATFINITE, __NV_E5M2);
}

// ---------------------------------------------------------------------------
// Kernel 1: fused row sums + A split (fp16 high / e4m3 full / e5m2 residual)
// ---------------------------------------------------------------------------
__global__ void rowsum_convert_kernel(const float* __restrict__ Mat) {
    __shared__ float red[256];
    int row = blockIdx.x;
    const float4* p = reinterpret_cast<const float4*>(Mat + (size_t)row * N_NODES);
    uint8_t* dst = g_A2 + (size_t)row * ROW_BYTES;
    float s = 0.f;
    for (int i = threadIdx.x; i < N_NODES / 8; i += 256) {
        float4 v0 = p[i * 2];
        float4 v1 = p[i * 2 + 1];
        s += (v0.x + v0.y) + (v0.z + v0.w) + (v1.x + v1.y) + (v1.z + v1.w);
        float f[8] = {v0.x, v0.y, v0.z, v0.w, v1.x, v1.y, v1.z, v1.w};
        uint32_t Hp[4];
        uint16_t pa[4], pl[4];
#pragma unroll
        for (int q = 0; q < 4; q++) {
            __half2 h2 = __floats2half2_rn(f[2 * q], f[2 * q + 1]);
            Hp[q] = *reinterpret_cast<uint32_t*>(&h2);
            float2 hf = __half22float2(h2);
            pa[q] = cvt2_e4m3(f[2 * q], f[2 * q + 1]);
            pl[q] = cvt2_e5m2(f[2 * q] - hf.x, f[2 * q + 1] - hf.y);
        }
        uint4 H;
        H.x = Hp[0]; H.y = Hp[1]; H.z = Hp[2]; H.w = Hp[3];
        uint64_t PA = (uint64_t)pa[0] | ((uint64_t)pa[1] << 16) |
                      ((uint64_t)pa[2] << 32) | ((uint64_t)pa[3] << 48);
        uint64_t PL = (uint64_t)pl[0] | ((uint64_t)pl[1] << 16) |
                      ((uint64_t)pl[2] << 32) | ((uint64_t)pl[3] << 48);
        int k = i * 8;
        int blk = k >> 5, pos = k & 31;
        uint8_t* b = dst + (size_t)blk * 128;
        *reinterpret_cast<uint4*>(b + pos * 2) = H;
        *reinterpret_cast<uint64_t*>(b + 64 + pos) = PA;
        *reinterpret_cast<uint64_t*>(b + 96 + pos) = PL;
    }
    red[threadIdx.x] = s;
    __syncthreads();
    for (int off = 128; off > 0; off >>= 1) {
        if (threadIdx.x < off) red[threadIdx.x] += red[threadIdx.x + off];
        __syncthreads();
    }
    if (threadIdx.x == 0) g_dinv[row] = rsqrtf(red[0] + 1e-8f);
}

// ---------------------------------------------------------------------------
// Kernel 2: B2[j] = split of (64 * F[k][j] * dinv[k])^T
// ---------------------------------------------------------------------------
__global__ void scale_transpose_kernel(const float* __restrict__ F) {
    __shared__ float tile[32][33];
    int jb = blockIdx.x * 32;
    int kb = blockIdx.y * 32;
    int tx = threadIdx.x;
    for (int r = threadIdx.y; r < 32; r += 8) {
        int k = kb + r;
        tile[r][tx] = F[(size_t)k * D_FEAT + jb + tx] * g_dinv[k];
    }
    __syncthreads();
    for (int r = threadIdx.y; r < 32; r += 8) {
        float a = tile[tx][r] * 64.0f;
        __half h = __float2half_rn(a);
        uint8_t* b = g_B2 + (size_t)(jb + r) * ROW_BYTES + (size_t)(kb >> 5) * 128;
        *reinterpret_cast<__half*>(b + tx * 2) = h;
        b[64 + tx] = f2e4m3(a);
        b[96 + tx] = f2e5m2(a - __half2float(h));
    }
}

// ---------------------------------------------------------------------------
// Kernel 3: cg2 (2-CTA) mixed fp16/fp8 3-pass tcgen05 GEMM, arrive-ahead.
//   Pair tile: M=512, N=256. Each CTA: A 32KB (256 rows), B 16KB (N/2 rows).
//   acc = Ah@Gh (f16) + A8@Gl8 + Al8@G8 ;  out = dinv_row * 2^-6 * acc
// ---------------------------------------------------------------------------
#define PAIR_M 512
#define TILE_N 256
#define STAGES 4
#define K_ITERS 256

#define A_STAGE_BYTES 32768              // 2 x 128 rows x 128B
#define B_STAGE_BYTES 16384              // 128 rows x 128B
#define STAGE_BYTES   (A_STAGE_BYTES + B_STAGE_BYTES)   // 48 KB
#define SMEM_AOF(s)   ((s) * STAGE_BYTES)
#define SMEM_BOF(s)   ((s) * STAGE_BYTES + A_STAGE_BYTES)
#define SMEM_CTRL     (STAGES * STAGE_BYTES)            // 196608
#define SMEM_TMEM_PTR (SMEM_CTRL)
#define SMEM_FULL(s)  (SMEM_CTRL + 16 + (s) * 8)
#define SMEM_DONE(s)  (SMEM_CTRL + 48 + (s) * 8)
#define SMEM_TOTAL    (SMEM_CTRL + 96 + 1024)

// idesc: cformat F32=1@[4:6), a/bformat@[7:10)/[10:13), N/8@[17:23), M/16@[24:29)
#define IDESC_F16 ((1u << 4) | ((TILE_N / 8) << 17) | ((256 / 16) << 24))
#define IDESC_F8(AT, BT) ((1u << 4) | ((AT) << 7) | ((BT) << 10) | ((TILE_N / 8) << 17) | ((256 / 16) << 24))

__device__ __forceinline__ uint32_t smem_u32(const void* p) {
    uint32_t a;
    asm("{ .reg .u64 t; cvta.to.shared.u64 t, %1; cvt.u32.u64 %0, t; }" : "=r"(a) : "l"(p));
    return a;
}
__device__ __forceinline__ uint32_t elect_one() {
    uint32_t pred;
    asm volatile("{\n\t.reg .pred p;\n\telect.sync _|p, 0xFFFFFFFF;\n\t"
                 "selp.b32 %0, 1, 0, p;\n\t}" : "=r"(pred));
    return pred;
}
__device__ __forceinline__ uint64_t make_desc(uint32_t addr) {
    constexpr uint64_t BASE = (uint64_t(2) << 61) | (uint64_t(1) << 46) |
                              (uint64_t(64) << 32) | (uint64_t(1) << 16);
    return BASE | ((uint64_t)(addr >> 4) & 0x3FFF);
}
__device__ __forceinline__ void cpasync16(uint32_t dst, const void* src) {
    asm volatile("cp.async.cg.shared.global [%0], [%1], 16;" :: "r"(dst), "l"(src));
}
__device__ __forceinline__ void mbar_wait(uint32_t mbar, uint32_t parity) {
    uint32_t done;
    asm volatile("{\n\t.reg .pred p;\n\t"
                 "mbarrier.try_wait.parity.acquire.cta.shared::cta.b64 p, [%1], %2;\n\t"
                 "selp.b32 %0, 1, 0, p;\n\t}"
                 : "=r"(done) : "r"(mbar), "r"(parity) : "memory");
    while (!done) {
        asm volatile("{\n\t.reg .pred p;\n\t"
                     "mbarrier.try_wait.parity.acquire.cta.shared::cta.b64 p, [%1], %2, 0x989680;\n\t"
                     "selp.b32 %0, 1, 0, p;\n\t}"
                     : "=r"(done) : "r"(mbar), "r"(parity) : "memory");
    }
}
// tid0-only: fence async proxy, then arrive on leader CTA's FULL(s) (local or remote).
__device__ __forceinline__ void arrive_full(uint32_t addr, uint32_t rank) {
    asm volatile("fence.proxy.async.shared::cta;" ::: "memory");
    if (rank == 0) {
        asm volatile("mbarrier.arrive.shared.b64 _, [%0];" :: "r"(addr) : "memory");
    } else {
        uint32_t rem;
        asm volatile("mapa.shared::cluster.u32 %0, %1, 0;" : "=r"(rem) : "r"(addr));
        asm volatile("mbarrier.arrive.shared::cluster.b64 _, [%0];" :: "r"(rem) : "memory");
    }
}

#if HAS_TCG
__device__ __forceinline__ void mma_f16_cg2(uint32_t d, uint64_t a, uint64_t b,
                                            uint32_t idesc, uint32_t enable) {
    asm volatile("{\n\t.reg .pred p;\n\tsetp.ne.u32 p, %4, 0;\n\t"
                 "tcgen05.mma.cta_group::2.kind::f16 [%0], %1, %2, %3, "
                 "{%5, %5, %5, %5, %5, %5, %5, %5}, p;\n\t}"
                 :: "r"(d), "l"(a), "l"(b), "r"(idesc), "r"(enable), "r"(0u) : "memory");
}
__device__ __forceinline__ void mma_f8_cg2(uint32_t d, uint64_t a, uint64_t b,
                                           uint32_t idesc, uint32_t enable) {
    asm volatile("{\n\t.reg .pred p;\n\tsetp.ne.u32 p, %4, 0;\n\t"
                 "tcgen05.mma.cta_group::2.kind::f8f6f4 [%0], %1, %2, %3, "
                 "{%5, %5, %5, %5, %5, %5, %5, %5}, p;\n\t}"
                 :: "r"(d), "l"(a), "l"(b), "r"(idesc), "r"(enable), "r"(0u) : "memory");
}
__device__ __forceinline__ void ldtm_x32(uint32_t* r, uint32_t taddr) {
    asm volatile(
        "tcgen05.ld.sync.aligned.32x32b.x32.b32 "
        "{%0, %1, %2, %3, %4, %5, %6, %7, "
        " %8, %9, %10, %11, %12, %13, %14, %15, "
        " %16, %17, %18, %19, %20, %21, %22, %23, "
        " %24, %25, %26, %27, %28, %29, %30, %31}, [%32];"
        : "=r"(r[0]),  "=r"(r[1]),  "=r"(r[2]),  "=r"(r[3]),
          "=r"(r[4]),  "=r"(r[5]),  "=r"(r[6]),  "=r"(r[7]),
          "=r"(r[8]),  "=r"(r[9]),  "=r"(r[10]), "=r"(r[11]),
          "=r"(r[12]), "=r"(r[13]), "=r"(r[14]), "=r"(r[15]),
          "=r"(r[16]), "=r"(r[17]), "=r"(r[18]), "=r"(r[19]),
          "=r"(r[20]), "=r"(r[21]), "=r"(r[22]), "=r"(r[23]),
          "=r"(r[24]), "=r"(r[25]), "=r"(r[26]), "=r"(r[27]),
          "=r"(r[28]), "=r"(r[29]), "=r"(r[30]), "=r"(r[31])
        : "r"(taddr));
}
#endif  // HAS_TCG

// Per-CTA stage load: A = 2 blocks of 128 rows (mma-half0/1), B = 128 rows.
__device__ __forceinline__ void load_stage(uint32_t smem_base, int s, int kiter,
                                           int a_row0, int a_row1, int b_row0, int tid) {
    uint32_t a0 = smem_base + SMEM_AOF(s);
    uint32_t b0 = smem_base + SMEM_BOF(s);
    const uint8_t* gA0 = g_A2 + (size_t)a_row0 * ROW_BYTES + (size_t)kiter * 128;
    const uint8_t* gA1 = g_A2 + (size_t)a_row1 * ROW_BYTES + (size_t)kiter * 128;
    const uint8_t* gB  = g_B2 + (size_t)b_row0 * ROW_BYTES + (size_t)kiter * 128;
#pragma unroll
    for (int i = 0; i < 8; i++) {
        int idx = tid + i * 128;
        int row = idx >> 3, c = idx & 7;
        uint32_t off = (uint32_t)row * 128 + c * 16;
        uint32_t sw = off ^ ((off >> 3) & 0x70);
        cpasync16(a0 + sw, gA0 + (size_t)row * ROW_BYTES + c * 16);
    }
#pragma unroll
    for (int i = 0; i < 8; i++) {
        int idx = tid + i * 128;
        int row = idx >> 3, c = idx & 7;
        uint32_t off = (uint32_t)row * 128 + c * 16;
        uint32_t sw = off ^ ((off >> 3) & 0x70);
        cpasync16(a0 + 16384 + sw, gA1 + (size_t)row * ROW_BYTES + c * 16);
    }
#pragma unroll
    for (int i = 0; i < 8; i++) {
        int idx = tid + i * 128;
        int row = idx >> 3, c = idx & 7;
        uint32_t off = (uint32_t)row * 128 + c * 16;
        uint32_t sw = off ^ ((off >> 3) & 0x70);
        cpasync16(b0 + sw, gB + (size_t)row * ROW_BYTES + c * 16);
    }
}

__global__ void __launch_bounds__(128, 1) __cluster_dims__(2, 1, 1)
gcn_gemm_kernel(float* __restrict__ out) {
#if HAS_TCG
    if (!g_has_tcg) return;
    extern __shared__ char smem[];
    uint32_t smem_base = (smem_u32(smem) + 1023u) & ~1023u;
    int tid = threadIdx.x;
    int wid = tid >> 5;
    int lid = tid & 31;
    uint32_t rank;
    asm("mov.u32 %0, %%cluster_ctarank;" : "=r"(rank));
    int pair = blockIdx.x >> 1;
    int mbase = pair * PAIR_M;
    int n0 = blockIdx.y * TILE_N;
    int a_row0 = mbase + (int)rank * 128;
    int a_row1 = mbase + 256 + (int)rank * 128;
    int b_row0 = n0 + (int)rank * 128;      // cg2 B split: N/2 rows per CTA

    if (tid == 0) {
#pragma unroll
        for (int s = 0; s < STAGES; s++) {
            asm volatile("mbarrier.init.shared.b64 [%0], %1;"
                         :: "r"(smem_base + SMEM_FULL(s)), "r"(2u) : "memory");
            asm volatile("mbarrier.init.shared.b64 [%0], %1;"
                         :: "r"(smem_base + SMEM_DONE(s)), "r"(1u) : "memory");
        }
    }
    if (wid == 0) {
        asm volatile("tcgen05.alloc.cta_group::2.sync.aligned.shared::cta.b32 [%0], %1;"
                     :: "r"(smem_base + SMEM_TMEM_PTR), "r"(512u) : "memory");
    }
    __syncthreads();
    asm volatile("barrier.cluster.arrive.aligned;" ::: "memory");
    asm volatile("barrier.cluster.wait.aligned;" ::: "memory");

    uint32_t tb;
    asm volatile("ld.shared.b32 %0, [%1];" : "=r"(tb) : "r"(smem_base + SMEM_TMEM_PTR));

    // Prologue: load stages 0..2; arrive-ahead for stage 0.
#pragma unroll
    for (int p = 0; p < STAGES - 1; p++) {
        load_stage(smem_base, p, p, a_row0, a_row1, b_row0, tid);
        asm volatile("cp.async.commit_group;" ::: "memory");
    }
    asm volatile("cp.async.wait_group 2;" ::: "memory");   // stage 0 complete
    __syncthreads();
    if (tid == 0) arrive_full(smem_base + SMEM_FULL(0), rank);

    for (int k = 0; k < K_ITERS; k++) {
        int s = k % STAGES;

        // Leader: FULL(s) was arrived during iter k-1 -> fast-path wait, issue MMAs.
        if (rank == 0 && wid == 0) {
            if (elect_one()) {
                mbar_wait(smem_base + SMEM_FULL(s), (uint32_t)((k / STAGES) & 1));
                uint32_t a_base = smem_base + SMEM_AOF(s);
                uint32_t b_base = smem_base + SMEM_BOF(s);
                uint64_t a0d = make_desc(a_base);           // pair M-half 0
                uint64_t a1d = make_desc(a_base + 16384);   // pair M-half 1
                uint64_t bd  = make_desc(b_base);
#pragma unroll
                for (int ks = 0; ks < 2; ks++) {            // fp16 Ah@Gh, K16 chunks
                    uint32_t en0 = (k > 0 || ks > 0) ? 1u : 0u;
                    mma_f16_cg2(tb,       a0d + 2 * ks, bd + 2 * ks, IDESC_F16, en0);
                    mma_f16_cg2(tb + 256, a1d + 2 * ks, bd + 2 * ks, IDESC_F16, en0);
                }
                mma_f8_cg2(tb,       a0d + 4, bd + 6, IDESC_F8(0, 1), 1u);   // A8@Gl8
                mma_f8_cg2(tb + 256, a1d + 4, bd + 6, IDESC_F8(0, 1), 1u);
                mma_f8_cg2(tb,       a0d + 6, bd + 4, IDESC_F8(1, 0), 1u);   // Al8@G8
                mma_f8_cg2(tb + 256, a1d + 6, bd + 4, IDESC_F8(1, 0), 1u);
                asm volatile(
                    "tcgen05.commit.cta_group::2.mbarrier::arrive::one.shared::cluster.multicast::cluster.b64 [%0], %1;"
                    :: "r"(smem_base + SMEM_DONE(s)), "h"((uint16_t)0x3) : "memory");
            }
        }

        // Refill stage kn = k+3 (waits iter k-1 MMA completion on that buffer).
        int kn = k + STAGES - 1;
        if (kn < K_ITERS) {
            if (k > 0) {
                int t = (k - 1) % STAGES;
                mbar_wait(smem_base + SMEM_DONE(t), (uint32_t)(((k - 1) / STAGES) & 1));
            }
            load_stage(smem_base, kn % STAGES, kn, a_row0, a_row1, b_row0, tid);
            asm volatile("cp.async.commit_group;" ::: "memory");
        }

        // Arrive-ahead for stage k+1 (its data is provably complete).
        if (k + 1 < K_ITERS) {
            int lastCommitted = (kn < K_ITERS) ? kn : (K_ITERS - 1);
            int pend = lastCommitted - (k + 1);   // 2, 1, or 0
            if (pend >= 2) {
                asm volatile("cp.async.wait_group 2;" ::: "memory");
            } else if (pend == 1) {
                asm volatile("cp.async.wait_group 1;" ::: "memory");
            } else {
                asm volatile("cp.async.wait_group 0;" ::: "memory");
            }
            __syncthreads();
            if (tid == 0)
                arrive_full(smem_base + SMEM_FULL((k + 1) % STAGES), rank);
        }
    }

    {
        int t = (K_ITERS - 1) % STAGES;
        mbar_wait(smem_base + SMEM_DONE(t), (uint32_t)(((K_ITERS - 1) / STAGES) & 1));
    }
    asm volatile("tcgen05.fence::after_thread_sync;" ::: "memory");

    // Epilogue: this CTA holds D rows rank*128.. of each pair M-half in its TMEM.
#pragma unroll
    for (int mh = 0; mh < 2; mh++) {
        int row = mbase + mh * 256 + (int)rank * 128 + wid * 32 + lid;
        float ds = g_dinv[row] * 0.015625f;
        float* orow = out + (size_t)row * D_FEAT + n0;
#pragma unroll
        for (int c = 0; c < 8; c++) {
            uint32_t r[32];
            ldtm_x32(r, tb + mh * 256 + c * 32);
            asm volatile("tcgen05.wait::ld.sync.aligned;" ::: "memory");
#pragma unroll
            for (int q = 0; q < 8; q++) {
                float4 v;
                v.x = __uint_as_float(r[q * 4 + 0]) * ds;
                v.y = __uint_as_float(r[q * 4 + 1]) * ds;
                v.z = __uint_as_float(r[q * 4 + 2]) * ds;
                v.w = __uint_as_float(r[q * 4 + 3]) * ds;
                *reinterpret_cast<float4*>(orow + c * 32 + q * 4) = v;
            }
        }
    }

    __syncthreads();
    if (wid == 0) {
        asm volatile("tcgen05.relinquish_alloc_permit.cta_group::2.sync.aligned;" ::: "memory");
        asm volatile("tcgen05.dealloc.cta_group::2.sync.aligned.b32 %0, %1;"
                     :: "r"(tb), "r"(512u));
    }
    asm volatile("barrier.cluster.arrive.aligned;" ::: "memory");
    asm volatile("barrier.cluster.wait.aligned;" ::: "memory");
#endif  // HAS_TCG
}

// ---------------------------------------------------------------------------
extern "C" void kernel_launch(void* const* d_in, const int* in_sizes, int n_in,
                              void* d_out, int out_size) {
    const float* features = (const float*)d_in[0];
    const float* Mat = (const float*)d_in[1];
    float* out = (float*)d_out;

    rowsum_convert_kernel<<<N_NODES, 256>>>(Mat);

    dim3 tpose_block(32, 8);
    dim3 tpose_grid(D_FEAT / 32, N_NODES / 32);
    scale_transpose_kernel<<<tpose_grid, tpose_block>>>(features);

    cudaFuncSetAttribute(gcn_gemm_kernel, cudaFuncAttributeMaxDynamicSharedMemorySize, SMEM_TOTAL);
    dim3 gemm_grid(N_NODES / PAIR_M * 2, D_FEAT / TILE_N);   // (32, 4), cluster (2,1)
    gcn_gemm_kernel<<<gemm_grid, 128, SMEM_TOTAL>>>(out);
}